// round 1
// baseline (speedup 1.0000x reference)
#include <cuda_runtime.h>
#include <cstddef>

// Problem constants (fixed by setup_inputs)
#define Bn 4
#define Sn 2048
#define Dn 1024
#define Hn 16
#define HDn 64
#define NBLK 8      // 8 blocks of 256 tokens (scales_idx = 256..2048)
#define BLKS 256

// Scratch for projected Q/K (device globals: allocation-free per harness rules)
__device__ float g_Q[(size_t)Bn * Sn * Dn];
__device__ float g_K[(size_t)Bn * Sn * Dn];

// ---------------------------------------------------------------------------
// GEMM: C[m,n] = sum_k x[m,k] * W[n,k] + bias[n]
//   M = B*S = 8192, K = 1024, N = 2048 (wq rows then wk rows)
//   Classic 128x128x8 fp32 SIMT tiling, 256 threads, 8x8 per-thread tile.
// ---------------------------------------------------------------------------
__global__ __launch_bounds__(256) void gemm_qk(
    const float* __restrict__ x,
    const float* __restrict__ wq, const float* __restrict__ wk,
    const float* __restrict__ bq, const float* __restrict__ bk)
{
    __shared__ float As[8][128];
    __shared__ float Bs[8][128];

    const int t  = threadIdx.x;
    const int bm = blockIdx.y;   // 0..63
    const int bn = blockIdx.x;   // 0..15
    const int tx = t & 15;       // 0..15 (n direction)
    const int ty = t >> 4;       // 0..15 (m direction)

    const int a_row = t >> 1;          // 0..127
    const int col4  = (t & 1) * 4;     // 0 or 4

    float acc[8][8];
    #pragma unroll
    for (int i = 0; i < 8; i++)
        #pragma unroll
        for (int j = 0; j < 8; j++) acc[i][j] = 0.f;

    const int n_row_g = bn * 128 + a_row;
    const float* brow = (n_row_g < Dn) ? (wq + (size_t)n_row_g * Dn)
                                       : (wk + (size_t)(n_row_g - Dn) * Dn);
    const float* arow = x + (size_t)(bm * 128 + a_row) * Dn;

    for (int k0 = 0; k0 < Dn; k0 += 8) {
        float4 av = *(const float4*)(arow + k0 + col4);
        float4 bv = *(const float4*)(brow + k0 + col4);
        As[col4 + 0][a_row] = av.x; As[col4 + 1][a_row] = av.y;
        As[col4 + 2][a_row] = av.z; As[col4 + 3][a_row] = av.w;
        Bs[col4 + 0][a_row] = bv.x; Bs[col4 + 1][a_row] = bv.y;
        Bs[col4 + 2][a_row] = bv.z; Bs[col4 + 3][a_row] = bv.w;
        __syncthreads();

        #pragma unroll
        for (int kk = 0; kk < 8; kk++) {
            float ar[8], br[8];
            #pragma unroll
            for (int i = 0; i < 8; i++) ar[i] = As[kk][ty * 8 + i];
            #pragma unroll
            for (int j = 0; j < 8; j++) br[j] = Bs[kk][tx * 8 + j];
            #pragma unroll
            for (int i = 0; i < 8; i++)
                #pragma unroll
                for (int j = 0; j < 8; j++) acc[i][j] += ar[i] * br[j];
        }
        __syncthreads();
    }

    // Epilogue: add bias, route to Q or K scratch
    #pragma unroll
    for (int i = 0; i < 8; i++) {
        const int m = bm * 128 + ty * 8 + i;
        #pragma unroll
        for (int j = 0; j < 8; j++) {
            const int n = bn * 128 + tx * 8 + j;
            if (n < Dn) g_Q[(size_t)m * Dn + n]        = acc[i][j] + bq[n];
            else        g_K[(size_t)m * Dn + (n - Dn)] = acc[i][j] + bk[n - Dn];
        }
    }
}

// ---------------------------------------------------------------------------
// Block-diagonal attention:
//   grid = (4 row-chunks, 8 blocks, 4 batches); 256 threads/CTA.
//   CTA handles 64 query rows of one 256-token block.
//   Thread (r = t/4, p = t%4) owns row r and the 64 keys j = p + 4*jl.
//   Per head: load K block (256x64) + Q rows (64x64) to SMEM, fp32 dot,
//   4-lane shfl softmax reduce, accumulate mean-over-heads in registers.
// ---------------------------------------------------------------------------
__global__ __launch_bounds__(256) void attn_kernel(float* __restrict__ out_w)
{
    extern __shared__ float sh[];
    float* k_sh = sh;                 // 256 * 65 floats (padded stride)
    float* q_sh = sh + 256 * 65;      // 64 * 65 floats

    const int t = threadIdx.x;
    const int r = t >> 2;             // 0..63  (query row within chunk)
    const int p = t & 3;              // 0..3   (key partition)
    const int b = blockIdx.z, blk = blockIdx.y, chunk = blockIdx.x;
    const int i0 = blk * BLKS + chunk * 64;

    float accw[64];
    #pragma unroll
    for (int jl = 0; jl < 64; jl++) accw[jl] = 0.f;

    for (int h = 0; h < Hn; h++) {
        __syncthreads();
        // Stage K block for this head: 256 rows x 64 dims
        #pragma unroll
        for (int it = 0; it < 16; it++) {
            const int idx = t + it * 256;
            const int j = idx >> 4, d4 = (idx & 15) << 2;
            float4 v = *(const float4*)&g_K[((size_t)(b * Sn + blk * BLKS + j)) * Dn + h * HDn + d4];
            k_sh[j * 65 + d4 + 0] = v.x; k_sh[j * 65 + d4 + 1] = v.y;
            k_sh[j * 65 + d4 + 2] = v.z; k_sh[j * 65 + d4 + 3] = v.w;
        }
        // Stage Q rows for this head: 64 rows x 64 dims
        #pragma unroll
        for (int it = 0; it < 4; it++) {
            const int idx = t + it * 256;
            const int rr = idx >> 4, d4 = (idx & 15) << 2;
            float4 v = *(const float4*)&g_Q[((size_t)(b * Sn + i0 + rr)) * Dn + h * HDn + d4];
            q_sh[rr * 65 + d4 + 0] = v.x; q_sh[rr * 65 + d4 + 1] = v.y;
            q_sh[rr * 65 + d4 + 2] = v.z; q_sh[rr * 65 + d4 + 3] = v.w;
        }
        __syncthreads();

        float q[64];
        #pragma unroll
        for (int d = 0; d < 64; d++) q[d] = q_sh[r * 65 + d];

        float s[64];
        #pragma unroll
        for (int jl = 0; jl < 64; jl++) {
            const float* kr = &k_sh[(p + 4 * jl) * 65];
            float sum = 0.f;
            #pragma unroll
            for (int d = 0; d < 64; d++) sum += q[d] * kr[d];
            s[jl] = sum * 0.125f;   // 1/sqrt(64)
        }

        // Row softmax across this thread's 64 keys + the 3 sibling lanes
        float m = -1e30f;
        #pragma unroll
        for (int jl = 0; jl < 64; jl++) m = fmaxf(m, s[jl]);
        m = fmaxf(m, __shfl_xor_sync(0xffffffffu, m, 1));
        m = fmaxf(m, __shfl_xor_sync(0xffffffffu, m, 2));

        float l = 0.f;
        #pragma unroll
        for (int jl = 0; jl < 64; jl++) { s[jl] = __expf(s[jl] - m); l += s[jl]; }
        l += __shfl_xor_sync(0xffffffffu, l, 1);
        l += __shfl_xor_sync(0xffffffffu, l, 2);

        const float w = (1.f / 16.f) / l;   // fold mean-over-heads
        #pragma unroll
        for (int jl = 0; jl < 64; jl++) accw[jl] += s[jl] * w;
    }

    // Write diagonal block entries: weights[b, i0+r, blk*256 + p + 4*jl]
    const size_t base = ((size_t)b * Sn + i0 + r) * Sn + blk * BLKS + p;
    #pragma unroll
    for (int jl = 0; jl < 64; jl++) out_w[base + 4 * jl] = accw[jl];
}

// ---------------------------------------------------------------------------
extern "C" void kernel_launch(void* const* d_in, const int* in_sizes, int n_in,
                              void* d_out, int out_size)
{
    const float* x  = (const float*)d_in[0];
    const float* wq = (const float*)d_in[1];
    const float* wk = (const float*)d_in[2];
    const float* bq = (const float*)d_in[3];
    const float* bk = (const float*)d_in[4];
    float* out = (float*)d_out;

    const size_t x_elems = (size_t)Bn * Sn * Dn;       //  8,388,608
    const size_t w_elems = (size_t)Bn * Sn * Sn;       // 16,777,216

    // Output layout: tuple (x, weights_attn) flattened. Be defensive on size.
    float* out_w;
    if ((size_t)out_size >= x_elems + w_elems) {
        cudaMemcpyAsync(out, x, x_elems * sizeof(float),
                        cudaMemcpyDeviceToDevice, 0);
        out_w = out + x_elems;
    } else {
        out_w = out;
    }
    // Off-diagonal weights are exactly zero (softmax of -inf)
    cudaMemsetAsync(out_w, 0, w_elems * sizeof(float), 0);

    // Projections
    dim3 ggrid(16, 64);
    gemm_qk<<<ggrid, 256>>>(x, wq, wk, bq, bk);

    // Block-diagonal softmax attention, mean over heads
    const size_t shbytes = (256 * 65 + 64 * 65) * sizeof(float);  // 83,200 B
    cudaFuncSetAttribute(attn_kernel,
                         cudaFuncAttributeMaxDynamicSharedMemorySize,
                         (int)shbytes);
    dim3 agrid(4, NBLK, Bn);
    attn_kernel<<<agrid, 256, shbytes>>>(out_w);
}

// round 3
// speedup vs baseline: 2.7171x; 2.7171x over previous
#include <cuda_runtime.h>
#include <cuda_bf16.h>
#include <cstdint>
#include <cstddef>

// Problem constants (fixed by setup_inputs)
#define Bn 4
#define Sn 2048
#define Dn 1024
#define Hn 16
#define HDn 64
#define NBLK 8
#define BLKS 256

#define GK 3072            // split-GEMM K: [hi|hi|lo] x [hi|lo|hi]
#define GM 8192            // B*S
#define GN 2048            // q rows then k rows
#define NCH (GK / 32)      // 96 K-chunks of 32

// ---------------------------------------------------------------------------
// Device scratch (allocation-free per harness rules)
// ---------------------------------------------------------------------------
__device__ __align__(256) float g_Q[(size_t)Bn * Sn * Dn];
__device__ __align__(256) float g_K[(size_t)Bn * Sn * Dn];
__device__ __align__(256) __nv_bfloat16 g_A[(size_t)GM * GK];   // 48 MB
__device__ __align__(256) __nv_bfloat16 g_W[(size_t)GN * GK];   // 12 MB

// ---------------------------------------------------------------------------
// Baseline-PTX helpers (no sm_103a-only features!)
// ---------------------------------------------------------------------------
__device__ __forceinline__ uint32_t smem_u32(const void* p) {
    uint32_t a;
    asm("{ .reg .u64 t; cvta.to.shared.u64 t, %1; cvt.u32.u64 %0, t; }"
        : "=r"(a) : "l"(p));
    return a;
}
__device__ __forceinline__ void cp16(uint32_t dst, const void* src) {
    asm volatile("cp.async.cg.shared.global [%0], [%1], 16;" :: "r"(dst), "l"(src));
}
#define CP_COMMIT() asm volatile("cp.async.commit_group;" ::: "memory")
#define CP_WAIT2()  asm volatile("cp.async.wait_group 2;" ::: "memory")

#define LDSM_X4(r, addr) \
    asm volatile("ldmatrix.sync.aligned.m8n8.x4.shared.b16 {%0,%1,%2,%3}, [%4];" \
        : "=r"((r)[0]), "=r"((r)[1]), "=r"((r)[2]), "=r"((r)[3]) : "r"(addr))

__device__ __forceinline__ void mma_bf16(float* c, const uint32_t* a,
                                         const uint32_t* b) {
    asm volatile(
        "mma.sync.aligned.m16n8k16.row.col.f32.bf16.bf16.f32 "
        "{%0,%1,%2,%3}, {%4,%5,%6,%7}, {%8,%9}, {%0,%1,%2,%3};"
        : "+f"(c[0]), "+f"(c[1]), "+f"(c[2]), "+f"(c[3])
        : "r"(a[0]), "r"(a[1]), "r"(a[2]), "r"(a[3]), "r"(b[0]), "r"(b[1]));
}

// ---------------------------------------------------------------------------
// Split kernels: fp32 -> (hi, lo) bf16, laid out for the K=3072 concat GEMM
//   A[m] = [hi(x) | hi(x) | lo(x)],  W[n] = [hi(w) | lo(w) | hi(w)]
//   (dropped lo*lo term is ~2^-18 relative)
// ---------------------------------------------------------------------------
__device__ __forceinline__ uint32_t pk2(__nv_bfloat16 a, __nv_bfloat16 b) {
    return (uint32_t)__bfloat16_as_ushort(a) | ((uint32_t)__bfloat16_as_ushort(b) << 16);
}

__global__ __launch_bounds__(256) void split_x(const float* __restrict__ x) {
    size_t i = ((size_t)blockIdx.x * 256 + threadIdx.x) * 8;
    float4 v0 = *(const float4*)(x + i);
    float4 v1 = *(const float4*)(x + i + 4);
    float v[8] = {v0.x, v0.y, v0.z, v0.w, v1.x, v1.y, v1.z, v1.w};
    __nv_bfloat16 h[8], l[8];
    #pragma unroll
    for (int e = 0; e < 8; e++) {
        h[e] = __float2bfloat16(v[e]);
        l[e] = __float2bfloat16(v[e] - __bfloat162float(h[e]));
    }
    uint4 H = {pk2(h[0], h[1]), pk2(h[2], h[3]), pk2(h[4], h[5]), pk2(h[6], h[7])};
    uint4 L = {pk2(l[0], l[1]), pk2(l[2], l[3]), pk2(l[4], l[5]), pk2(l[6], l[7])};
    size_t m = i >> 10, k = i & 1023;
    __nv_bfloat16* row = g_A + m * GK;
    *(uint4*)(row + k)        = H;
    *(uint4*)(row + 1024 + k) = H;
    *(uint4*)(row + 2048 + k) = L;
}

__global__ __launch_bounds__(256) void split_w(const float* __restrict__ wq,
                                               const float* __restrict__ wk) {
    size_t i = ((size_t)blockIdx.x * 256 + threadIdx.x) * 8;
    size_t n = i >> 10, k = i & 1023;
    const float* src = (n < 1024) ? (wq + n * 1024 + k) : (wk + (n - 1024) * 1024 + k);
    float4 v0 = *(const float4*)src;
    float4 v1 = *(const float4*)(src + 4);
    float v[8] = {v0.x, v0.y, v0.z, v0.w, v1.x, v1.y, v1.z, v1.w};
    __nv_bfloat16 h[8], l[8];
    #pragma unroll
    for (int e = 0; e < 8; e++) {
        h[e] = __float2bfloat16(v[e]);
        l[e] = __float2bfloat16(v[e] - __bfloat162float(h[e]));
    }
    uint4 H = {pk2(h[0], h[1]), pk2(h[2], h[3]), pk2(h[4], h[5]), pk2(h[6], h[7])};
    uint4 L = {pk2(l[0], l[1]), pk2(l[2], l[3]), pk2(l[4], l[5]), pk2(l[6], l[7])};
    __nv_bfloat16* row = g_W + n * GK;
    *(uint4*)(row + k)        = H;
    *(uint4*)(row + 1024 + k) = L;
    *(uint4*)(row + 2048 + k) = H;
}

// ---------------------------------------------------------------------------
// mma.sync bf16 GEMM: C[8192 x 2048] = A_split . W_split^T  (+bias, ->g_Q/g_K)
//   CTA 128x128, K-chunk 32, 4-stage cp.async pipeline.
//   SMEM rows padded to 80B (stride/4=20 -> 8 ldmatrix rows hit 8 distinct
//   bank groups: r*20 mod 32 = {0,20,8,28,16,4,24,12}).
//   8 warps: mw = wid&3 (32 rows), nw = wid>>2 (64 cols).
// ---------------------------------------------------------------------------
#define RS 80                      // smem row stride bytes (32 bf16 + pad)
#define STAGE (128 * RS * 2)       // A(10240) + B(10240) = 20480
#define GEMM_SMEM (4 * STAGE)      // 81920

__global__ __launch_bounds__(256, 2) void gemm_tc(
    const float* __restrict__ bq, const float* __restrict__ bk)
{
    extern __shared__ char smem[];
    const uint32_t smb = smem_u32(smem);
    const int tid  = threadIdx.x;
    const int wid  = tid >> 5;
    const int lane = tid & 31;
    const int mw = wid & 3;        // m warp (32 rows)
    const int nw = wid >> 2;       // n warp (64 cols)
    const int bn = blockIdx.x;     // 0..15
    const int bm = blockIdx.y;     // 0..63

    float c[2][8][4];
    #pragma unroll
    for (int mt = 0; mt < 2; mt++)
        #pragma unroll
        for (int nt = 0; nt < 8; nt++)
            #pragma unroll
            for (int e = 0; e < 4; e++) c[mt][nt][e] = 0.f;

    // ldmatrix lane-offset bases (within a stage)
    const uint32_t a_base = (uint32_t)((mw * 32 + (lane & 15)) * RS + (lane >> 4) * 16);
    const uint32_t b_base = (uint32_t)(128 * RS +
        (nw * 64 + ((lane >> 4) & 1) * 8 + (lane & 7)) * RS + ((lane >> 3) & 1) * 16);

    // stage loader: A(128x32) + B(128x32) bf16 for chunk kc into slot
    auto stage = [&](int slot, int kc) {
        const uint32_t sb = smb + slot * STAGE;
        const size_t koff = (size_t)kc * 32;
        #pragma unroll
        for (int i = 0; i < 4; i++) {
            const int idx = tid + i * 256;      // 0..1023
            const int row = idx >> 2, cc = idx & 3;
            if (row < 128) {
                cp16(sb + row * RS + cc * 16,
                     g_A + (size_t)(bm * 128 + row) * GK + koff + cc * 8);
            } else {
                const int r2 = row - 128;
                cp16(sb + 128 * RS + r2 * RS + cc * 16,
                     g_W + (size_t)(bn * 128 + r2) * GK + koff + cc * 8);
            }
        }
    };

    #pragma unroll
    for (int s = 0; s < 3; s++) { stage(s, s); CP_COMMIT(); }

    for (int kc = 0; kc < NCH; kc++) {
        const uint32_t sb = smb + (kc & 3) * STAGE;
        CP_WAIT2();
        __syncthreads();

        #pragma unroll
        for (int ks = 0; ks < 2; ks++) {
            uint32_t a0[4], a1[4], b0[4], b1[4], b2[4], b3[4];
            LDSM_X4(a0, sb + a_base + ks * 32);
            LDSM_X4(a1, sb + a_base + 16 * RS + ks * 32);
            LDSM_X4(b0, sb + b_base + ks * 32);
            LDSM_X4(b1, sb + b_base + 16 * RS + ks * 32);
            LDSM_X4(b2, sb + b_base + 32 * RS + ks * 32);
            LDSM_X4(b3, sb + b_base + 48 * RS + ks * 32);
            const uint32_t* bp[4] = {b0, b1, b2, b3};
            #pragma unroll
            for (int mt = 0; mt < 2; mt++) {
                const uint32_t* a = mt ? a1 : a0;
                #pragma unroll
                for (int nt = 0; nt < 8; nt++)
                    mma_bf16(c[mt][nt], a, bp[nt >> 1] + (nt & 1) * 2);
            }
        }
        __syncthreads();
        if (kc + 3 < NCH) stage((kc + 3) & 3, kc + 3);
        CP_COMMIT();
    }

    // Epilogue: bias + route to g_Q / g_K
    const int colloc = (bn & 7) * 128 + nw * 64 + (lane & 3) * 2;
    const float* bias = ((bn < 8) ? bq : bk);
    float* gout = (bn < 8) ? g_Q : g_K;
    float2 bv[8];
    #pragma unroll
    for (int nt = 0; nt < 8; nt++)
        bv[nt] = *(const float2*)(bias + colloc + nt * 8);

    #pragma unroll
    for (int mt = 0; mt < 2; mt++) {
        #pragma unroll
        for (int h = 0; h < 2; h++) {
            const int row = bm * 128 + mw * 32 + mt * 16 + h * 8 + (lane >> 2);
            float* dst = gout + (size_t)row * Dn + colloc;
            #pragma unroll
            for (int nt = 0; nt < 8; nt++) {
                float2 v;
                v.x = c[mt][nt][h * 2 + 0] + bv[nt].x;
                v.y = c[mt][nt][h * 2 + 1] + bv[nt].y;
                *(float2*)(dst + nt * 8) = v;
            }
        }
    }
}

// ---------------------------------------------------------------------------
// Block-diagonal attention:
//   grid (8 chunks, 8 blocks, 4 batches); 256 threads.
//   CTA: 32 query rows of one 256-token block.
//   Warp w: rp = w (rows 4w..4w+3), lane kp = keys kp + 32*jl (jl 0..7).
//   K tile XOR-swizzled in smem (chunk d4 ^ (j&15)) -> conflict-free phases.
//   4 rows x 8 keys per thread: 128 FMA per 12 LDS.128 -> FMA-bound.
// ---------------------------------------------------------------------------
#define ATTN_SMEM ((256 * 64 + 32 * 64) * 4)   // 73,728

__global__ __launch_bounds__(256, 2) void attn_kernel(float* __restrict__ out_w)
{
    extern __shared__ float sh[];
    float* k_sh = sh;                 // 256 x 64, swizzled
    float* q_sh = sh + 256 * 64;      // 32 x 64, plain (broadcast reads)

    const int t  = threadIdx.x;
    const int rp = t >> 5;            // warp id = row group (4 rows)
    const int kp = t & 31;            // key lane
    const int b = blockIdx.z, blk = blockIdx.y, chunk = blockIdx.x;
    const int i0 = blk * BLKS + chunk * 32;

    float accw[4][8];
    #pragma unroll
    for (int i = 0; i < 4; i++)
        #pragma unroll
        for (int jl = 0; jl < 8; jl++) accw[i][jl] = 0.f;

    for (int h = 0; h < Hn; h++) {
        __syncthreads();
        // stage K: 256 rows x 64 dims, swizzle chunk c' = c ^ (j & 15)
        #pragma unroll
        for (int it = 0; it < 16; it++) {
            const int idx = t + it * 256;
            const int j = idx >> 4, cc = idx & 15;
            float4 v = *(const float4*)&g_K[((size_t)(b * Sn + blk * BLKS + j)) * Dn + h * HDn + cc * 4];
            *(float4*)&k_sh[j * 64 + ((cc ^ (j & 15)) << 2)] = v;
        }
        // stage Q: 32 rows x 64 dims, plain
        #pragma unroll
        for (int it = 0; it < 2; it++) {
            const int idx = t + it * 256;
            const int rr = idx >> 4, cc = idx & 15;
            float4 v = *(const float4*)&g_Q[((size_t)(b * Sn + i0 + rr)) * Dn + h * HDn + cc * 4];
            *(float4*)&q_sh[rr * 64 + cc * 4] = v;
        }
        __syncthreads();

        float s[4][8];
        #pragma unroll
        for (int i = 0; i < 4; i++)
            #pragma unroll
            for (int jl = 0; jl < 8; jl++) s[i][jl] = 0.f;

        const int sw = kp & 15;
        #pragma unroll 4
        for (int d4 = 0; d4 < 16; d4++) {
            float4 qv[4];
            #pragma unroll
            for (int i = 0; i < 4; i++)
                qv[i] = *(const float4*)&q_sh[(rp * 4 + i) * 64 + d4 * 4];
            #pragma unroll
            for (int jl = 0; jl < 8; jl++) {
                const int j = kp + 32 * jl;
                float4 kv = *(const float4*)&k_sh[j * 64 + ((d4 ^ sw) << 2)];
                #pragma unroll
                for (int i = 0; i < 4; i++) {
                    s[i][jl] += kv.x * qv[i].x + kv.y * qv[i].y
                              + kv.z * qv[i].z + kv.w * qv[i].w;
                }
            }
        }

        // softmax per row (8 local keys + 32-lane warp reduce), fold 1/16 mean
        #pragma unroll
        for (int i = 0; i < 4; i++) {
            float m = -1e30f;
            #pragma unroll
            for (int jl = 0; jl < 8; jl++) { s[i][jl] *= 0.125f; m = fmaxf(m, s[i][jl]); }
            #pragma unroll
            for (int w = 1; w < 32; w <<= 1)
                m = fmaxf(m, __shfl_xor_sync(0xffffffffu, m, w));
            float l = 0.f;
            #pragma unroll
            for (int jl = 0; jl < 8; jl++) { s[i][jl] = __expf(s[i][jl] - m); l += s[i][jl]; }
            #pragma unroll
            for (int w = 1; w < 32; w <<= 1)
                l += __shfl_xor_sync(0xffffffffu, l, w);
            const float inv = (1.f / 16.f) / l;
            #pragma unroll
            for (int jl = 0; jl < 8; jl++) accw[i][jl] += s[i][jl] * inv;
        }
    }

    // write: weights[b, i0 + 4rp + i, blk*256 + kp + 32*jl]
    #pragma unroll
    for (int i = 0; i < 4; i++) {
        const size_t base = ((size_t)(b * Sn + i0 + rp * 4 + i)) * Sn + blk * BLKS + kp;
        #pragma unroll
        for (int jl = 0; jl < 8; jl++) out_w[base + 32 * jl] = accw[i][jl];
    }
}

// ---------------------------------------------------------------------------
extern "C" void kernel_launch(void* const* d_in, const int* in_sizes, int n_in,
                              void* d_out, int out_size)
{
    const float* x  = (const float*)d_in[0];
    const float* wq = (const float*)d_in[1];
    const float* wk = (const float*)d_in[2];
    const float* bq = (const float*)d_in[3];
    const float* bk = (const float*)d_in[4];
    float* out = (float*)d_out;

    const size_t x_elems = (size_t)Bn * Sn * Dn;   //  8,388,608
    const size_t w_elems = (size_t)Bn * Sn * Sn;   // 16,777,216

    float* out_w;
    if ((size_t)out_size >= x_elems + w_elems) {
        cudaMemcpyAsync(out, x, x_elems * sizeof(float),
                        cudaMemcpyDeviceToDevice, 0);
        out_w = out + x_elems;
    } else {
        out_w = out;
    }
    cudaMemsetAsync(out_w, 0, w_elems * sizeof(float), 0);

    // bf16 hi/lo splits
    split_x<<<(int)(x_elems / (256 * 8)), 256>>>(x);
    split_w<<<(int)(((size_t)GN * Dn) / (256 * 8)), 256>>>(wq, wk);

    // mma.sync projection GEMM
    cudaFuncSetAttribute(gemm_tc, cudaFuncAttributeMaxDynamicSharedMemorySize,
                         GEMM_SMEM);
    dim3 ggrid(16, 64);
    gemm_tc<<<ggrid, 256, GEMM_SMEM>>>(bq, bk);

    // block-diagonal softmax attention (mean over heads folded in)
    cudaFuncSetAttribute(attn_kernel, cudaFuncAttributeMaxDynamicSharedMemorySize,
                         ATTN_SMEM);
    dim3 agrid(8, NBLK, Bn);
    attn_kernel<<<agrid, 256, ATTN_SMEM>>>(out_w);
}